// round 1
// baseline (speedup 1.0000x reference)
#include <cuda_runtime.h>

// Problem shape (fixed by dataset)
#define BS 8
#define SS 256
#define HH 768
#define KK 256
#define PP 50

// Scratch: left[b,s,k], right[b,s,k] (b_s folded into right). 2 MB each.
__device__ float g_left[BS * SS * KK];
__device__ float g_right[BS * SS * KK];

// Packed dual-FMA: fma.rn.f32x2 (sm_100+). ptxas never auto-fuses this from C++.
__device__ __forceinline__ float2 ffma2(const float2 a, const float2 b, const float2 c) {
    float2 r;
    asm("fma.rn.f32x2 %0, %1, %2, %3;"
        : "=l"(reinterpret_cast<unsigned long long &>(r))
        : "l"(reinterpret_cast<const unsigned long long &>(a)),
          "l"(reinterpret_cast<const unsigned long long &>(b)),
          "l"(reinterpret_cast<const unsigned long long &>(c)));
    return r;
}

// Accurate-enough fast tanh: 2 MUFU + ~4 fma-pipe ops, rel err ~1e-6.
// Robust at extremes: s->+inf: e=inf, rcp=0, t=1. s->-inf: e=0, t=-1.
__device__ __forceinline__ float tanh_fast(float s) {
    float e = __expf(s + s);          // FADD + FMUL + MUFU.EX2
    float r;
    asm("rcp.approx.f32 %0, %1;" : "=f"(r) : "f"(e + 1.0f));
    return fmaf(-2.0f, r, 1.0f);
}

// ---------------------------------------------------------------------------
// Kernel 1: projections. z=0: g_left = x @ u_a ; z=1: g_right = x @ w_a + b_s
// M = B*S = 2048 rows, N = K = 256 cols, inner = H = 768.
// 64x64 tile per block, 256 threads, 4x4 micro-tile per thread, f32x2 FMAs.
// ---------------------------------------------------------------------------
__global__ __launch_bounds__(256) void proj_kernel(
    const float* __restrict__ x, const float* __restrict__ u_a,
    const float* __restrict__ w_a, const float* __restrict__ b_s)
{
    const int zz = blockIdx.z;
    const float* __restrict__ W = zz ? w_a : u_a;
    float* __restrict__ O = zz ? g_right : g_left;
    const int m0 = blockIdx.y * 64;
    const int k0 = blockIdx.x * 64;

    __shared__ float As[16 * 68];                 // [hh][mm], padded
    __shared__ __align__(16) float Bsm[16 * 64];  // [hh][kk]

    const int tid = threadIdx.x;
    const int tx = tid & 15;   // output col group
    const int ty = tid >> 4;   // output row group

    float2 acc[4][2];
#pragma unroll
    for (int r = 0; r < 4; r++) {
        acc[r][0] = make_float2(0.f, 0.f);
        acc[r][1] = make_float2(0.f, 0.f);
    }

    for (int h0 = 0; h0 < HH; h0 += 16) {
#pragma unroll
        for (int l = 0; l < 4; l++) {
            int idx = tid + l * 256;              // 0..1023
            int mm = idx >> 4, hh = idx & 15;     // A tile: 64 rows x 16 h (transposed store)
            As[hh * 68 + mm] = x[(m0 + mm) * HH + h0 + hh];
        }
#pragma unroll
        for (int l = 0; l < 4; l++) {
            int idx = tid + l * 256;
            int hh = idx >> 6, kk = idx & 63;     // B tile: 16 h x 64 k (coalesced)
            Bsm[hh * 64 + kk] = W[(h0 + hh) * KK + k0 + kk];
        }
        __syncthreads();

#pragma unroll
        for (int hh = 0; hh < 16; hh++) {
            float4 b4 = *(const float4*)&Bsm[hh * 64 + tx * 4];
            float2 b0 = make_float2(b4.x, b4.y);
            float2 b1 = make_float2(b4.z, b4.w);
#pragma unroll
            for (int r = 0; r < 4; r++) {
                float a = As[hh * 68 + ty * 4 + r];
                float2 a2 = make_float2(a, a);
                acc[r][0] = ffma2(a2, b0, acc[r][0]);
                acc[r][1] = ffma2(a2, b1, acc[r][1]);
            }
        }
        __syncthreads();
    }

    float2 bs01 = make_float2(0.f, 0.f), bs23 = make_float2(0.f, 0.f);
    if (zz) {
        bs01 = *(const float2*)&b_s[k0 + tx * 4];
        bs23 = *(const float2*)&b_s[k0 + tx * 4 + 2];
    }
#pragma unroll
    for (int r = 0; r < 4; r++) {
        int m = m0 + ty * 4 + r;
        float2 v0 = acc[r][0], v1 = acc[r][1];
        v0.x += bs01.x; v0.y += bs01.y;
        v1.x += bs23.x; v1.y += bs23.y;
        float2* op = (float2*)&O[m * KK + k0 + tx * 4];
        op[0] = v0;
        op[1] = v1;
    }
}

// ---------------------------------------------------------------------------
// Kernel 2: out[b,i,j,p] = sum_k tanh(left[b,i,k] + right[b,j,k]) * v[k,p]
// Block = 16x16 (i,j) tile, 256 threads, one (i,j) per thread.
// 25 float2 accumulators (P=50). k chunked by 64; left/right/v staged in smem.
// fma-pipe bound: 25 FFMA2 per k per thread.
// ---------------------------------------------------------------------------
#define TI 16
#define TJ 16
#define KC 64

__global__ __launch_bounds__(256) void mhs_kernel(
    const float* __restrict__ v, float* __restrict__ out)
{
    __shared__ float ls[TI * (KC + 1)];               // stride 65 -> conflict-free
    __shared__ float rs[TJ * (KC + 1)];
    __shared__ __align__(16) float vs[KC * PP];       // 64 x 50 = 12.8 KB

    const int b  = blockIdx.z;
    const int i0 = blockIdx.y * TI;
    const int j0 = blockIdx.x * TJ;
    const int tid = threadIdx.x;
    const int jj = tid & 15;
    const int ii = tid >> 4;

    float2 acc[PP / 2];
#pragma unroll
    for (int p = 0; p < PP / 2; p++) acc[p] = make_float2(0.f, 0.f);

    const float* __restrict__ lbase = g_left  + (b * SS + i0) * KK;
    const float* __restrict__ rbase = g_right + (b * SS + j0) * KK;

    for (int k0 = 0; k0 < KK; k0 += KC) {
#pragma unroll
        for (int l = 0; l < 4; l++) {
            int idx = tid + l * 256;                  // 0..1023 = 16 rows x 64 k
            int row = idx >> 6, kk = idx & 63;
            ls[row * (KC + 1) + kk] = lbase[row * KK + k0 + kk];
            rs[row * (KC + 1) + kk] = rbase[row * KK + k0 + kk];
        }
        for (int idx = tid; idx < KC * PP; idx += 256)
            vs[idx] = v[k0 * PP + idx];               // contiguous rows of v
        __syncthreads();

#pragma unroll 8
        for (int kk = 0; kk < KC; kk++) {
            float s = ls[ii * (KC + 1) + kk] + rs[jj * (KC + 1) + kk];
            float t = tanh_fast(s);
            float2 t2 = make_float2(t, t);
            const float2* vr = (const float2*)(vs + kk * PP);  // 8B aligned (PP even)
#pragma unroll
            for (int p = 0; p < PP / 2; p++)
                acc[p] = ffma2(t2, vr[p], acc[p]);
        }
        __syncthreads();
    }

    float2* op = (float2*)(out + (size_t)(((b * SS + i0 + ii) * SS) + j0 + jj) * PP);
#pragma unroll
    for (int p = 0; p < PP / 2; p++) op[p] = acc[p];
}

// ---------------------------------------------------------------------------
// Launch. Inputs (metadata order): x, u_a, w_a, b_s, v. Output: float32.
// Graph-capturable: two kernel launches on the default stream, no allocs.
// ---------------------------------------------------------------------------
extern "C" void kernel_launch(void* const* d_in, const int* in_sizes, int n_in,
                              void* d_out, int out_size)
{
    const float* x   = (const float*)d_in[0];
    const float* u_a = (const float*)d_in[1];
    const float* w_a = (const float*)d_in[2];
    const float* b_s = (const float*)d_in[3];
    const float* v   = (const float*)d_in[4];
    float* out = (float*)d_out;

    // Kernel 1: projections into scratch. Grid: (K/64, M/64, 2)
    dim3 g1(KK / 64, (BS * SS) / 64, 2);
    proj_kernel<<<g1, 256>>>(x, u_a, w_a, b_s);

    // Kernel 2: main fused tanh-GEMM. Grid: (S/TJ, S/TI, B)
    dim3 g2(SS / TJ, SS / TI, BS);
    mhs_kernel<<<g2, 256>>>(v, out);
}

// round 4
// speedup vs baseline: 2.5134x; 2.5134x over previous
#include <cuda_runtime.h>
#include <cstdint>

// Problem shape (fixed by dataset)
#define BS 8
#define SS 256
#define HH 768
#define KK 256
#define PP 50

// Scratch: left[b,s,k], right[b,s,k] (b_s folded into right). 2 MB each.
__device__ float g_left[BS * SS * KK];
__device__ float g_right[BS * SS * KK];

// ---------------------------------------------------------------------------
// Helpers
// ---------------------------------------------------------------------------
__device__ __forceinline__ float2 ffma2(const float2 a, const float2 b, const float2 c) {
    float2 r;
    asm("fma.rn.f32x2 %0, %1, %2, %3;"
        : "=l"(reinterpret_cast<unsigned long long &>(r))
        : "l"(reinterpret_cast<const unsigned long long &>(a)),
          "l"(reinterpret_cast<const unsigned long long &>(b)),
          "l"(reinterpret_cast<const unsigned long long &>(c)));
    return r;
}

// Input z is PRE-SCALED: z = 2*log2(e)*s. tanh(s) = 1 - 2/(2^z + 1).
// Robust: z->+inf: e=inf -> rcp 0 -> 1 ; z->-inf: e=0 -> rcp(1)=1 -> -1.
// Returns tf32-rounded bits (A operand for mma).
__device__ __forceinline__ uint32_t tanh_tf32(float z) {
    float e;
    asm("ex2.approx.f32 %0, %1;" : "=f"(e) : "f"(z));
    float r;
    asm("rcp.approx.f32 %0, %1;" : "=f"(r) : "f"(e + 1.0f));
    float t = fmaf(-2.0f, r, 1.0f);
    uint32_t u;
    asm("cvt.rna.tf32.f32 %0, %1;" : "=r"(u) : "f"(t));
    return u;
}

__device__ __forceinline__ uint32_t f2tf32(float x) {
    uint32_t r;
    asm("cvt.rna.tf32.f32 %0, %1;" : "=r"(r) : "f"(x));
    return r;
}

// m16n8k8 tf32 MMA, D += A*B (base ISA, sm_80+; no 'a' features needed)
__device__ __forceinline__ void mma_tf32(float* c, uint32_t a0, uint32_t a1,
                                         uint32_t a2, uint32_t a3,
                                         uint32_t b0, uint32_t b1) {
    asm volatile("mma.sync.aligned.m16n8k8.row.col.f32.tf32.tf32.f32 "
                 "{%0,%1,%2,%3}, {%4,%5,%6,%7}, {%8,%9}, {%0,%1,%2,%3};"
                 : "+f"(c[0]), "+f"(c[1]), "+f"(c[2]), "+f"(c[3])
                 : "r"(a0), "r"(a1), "r"(a2), "r"(a3), "r"(b0), "r"(b1));
}

// ---------------------------------------------------------------------------
// Kernel 1: projections. z=0: g_left = x @ u_a ; z=1: g_right = x @ w_a + b_s
// (unchanged; ~38us fma-bound)
// ---------------------------------------------------------------------------
__global__ __launch_bounds__(256) void proj_kernel(
    const float* __restrict__ x, const float* __restrict__ u_a,
    const float* __restrict__ w_a, const float* __restrict__ b_s)
{
    const int zz = blockIdx.z;
    const float* __restrict__ W = zz ? w_a : u_a;
    float* __restrict__ O = zz ? g_right : g_left;
    const int m0 = blockIdx.y * 64;
    const int k0 = blockIdx.x * 64;

    __shared__ float As[16 * 68];
    __shared__ __align__(16) float Bsm[16 * 64];

    const int tid = threadIdx.x;
    const int tx = tid & 15;
    const int ty = tid >> 4;

    float2 acc[4][2];
#pragma unroll
    for (int r = 0; r < 4; r++) {
        acc[r][0] = make_float2(0.f, 0.f);
        acc[r][1] = make_float2(0.f, 0.f);
    }

    for (int h0 = 0; h0 < HH; h0 += 16) {
#pragma unroll
        for (int l = 0; l < 4; l++) {
            int idx = tid + l * 256;
            int mm = idx >> 4, hh = idx & 15;
            As[hh * 68 + mm] = x[(m0 + mm) * HH + h0 + hh];
        }
#pragma unroll
        for (int l = 0; l < 4; l++) {
            int idx = tid + l * 256;
            int hh = idx >> 6, kk = idx & 63;
            Bsm[hh * 64 + kk] = W[(h0 + hh) * KK + k0 + kk];
        }
        __syncthreads();

#pragma unroll
        for (int hh = 0; hh < 16; hh++) {
            float4 b4 = *(const float4*)&Bsm[hh * 64 + tx * 4];
            float2 b0 = make_float2(b4.x, b4.y);
            float2 b1 = make_float2(b4.z, b4.w);
#pragma unroll
            for (int r = 0; r < 4; r++) {
                float a = As[hh * 68 + ty * 4 + r];
                float2 a2 = make_float2(a, a);
                acc[r][0] = ffma2(a2, b0, acc[r][0]);
                acc[r][1] = ffma2(a2, b1, acc[r][1]);
            }
        }
        __syncthreads();
    }

    float2 bs01 = make_float2(0.f, 0.f), bs23 = make_float2(0.f, 0.f);
    if (zz) {
        bs01 = *(const float2*)&b_s[k0 + tx * 4];
        bs23 = *(const float2*)&b_s[k0 + tx * 4 + 2];
    }
#pragma unroll
    for (int r = 0; r < 4; r++) {
        int m = m0 + ty * 4 + r;
        float2 v0 = acc[r][0], v1 = acc[r][1];
        v0.x += bs01.x; v0.y += bs01.y;
        v1.x += bs23.x; v1.y += bs23.y;
        float2* op = (float2*)&O[m * KK + k0 + tx * 4];
        op[0] = v0;
        op[1] = v1;
    }
}

// ---------------------------------------------------------------------------
// Kernel 2: out[b,i,j,p] = sum_k tanh(left[b,i,k]+right[b,j,k]) * v[k,p]
// via mma.sync m16n8k8 tf32.
//   Tile = 16 i x 16 j (256 ij rows). Warp w owns i = i0+w, all 16 j.
//   A (16x8 per kstep) = tanh values, computed straight into fragment regs:
//     a0:(j=gp,   k=kq)  a1:(j=gp+8, k=kq)  a2:(j=gp, k=kq+4)  a3:(j=gp+8, k=kq+4)
//   B = v (tf32, smem, stride 56 -> conflict-free: bank=(24k+n)%32 all distinct)
//   7 n-tiles cover P=50 (pad 56). acc = 7x4 f32.
// Persistent 148 blocks x 512 threads. No syncs inside the k-loop.
// ---------------------------------------------------------------------------
#define TI 16
#define TJ 16
#define NT 7                    // n-tiles of 8 (56 >= 50)
#define NTILES 2048             // BS * (SS/TI) * (SS/TJ)
#define THR 512
#define RC_STR 260              // right smem stride: bank=(4*gp+kq)%32 distinct

// Dynamic smem layout (floats)
#define SV 0                    // v tf32: 256 x 56            = 14336
#define SL (SV + KK * 56)       // left  (scaled): 16 x 256    = 4096
#define SR (SL + TI * KK)       // right (scaled): 16 x 260    = 4160
#define SM_FLOATS (SR + TJ * RC_STR)
#define SM_BYTES (SM_FLOATS * 4)   // ~90 KB

__global__ __launch_bounds__(THR, 1) void mhs_mma_kernel(
    const float* __restrict__ v, float* __restrict__ out)
{
    extern __shared__ float sm[];
    uint32_t* v_s = (uint32_t*)(sm + SV);
    float* lc_s = sm + SL;
    float* rc_s = sm + SR;

    const int tid = threadIdx.x;
    const int w = tid >> 5;
    const int lane = tid & 31;
    const int kq = lane & 3;        // k within quad
    const int gp = lane >> 2;       // group id (j / n offset)
    const float cs = 2.885390081777927f;   // 2*log2(e)

    // Stage v as tf32, padded to 56 cols (zeros beyond P=50). Once per block.
    for (int idx = tid; idx < KK * 56; idx += THR) {
        int k = idx / 56, n = idx - k * 56;
        float val = (n < PP) ? v[k * PP + n] : 0.0f;
        v_s[idx] = f2tf32(val);
    }

    for (int t = blockIdx.x; t < NTILES; t += gridDim.x) {
        const int b = t >> 8;
        const int rem = t & 255;
        const int i0 = (rem >> 4) * TI;
        const int j0 = (rem & 15) * TJ;

        __syncthreads();   // protect lc/rc from laggard readers of previous tile

        // Stage left/right rows, pre-scaled by 2*log2(e)
        {
            const float4* lg = (const float4*)(g_left + (b * SS + i0) * KK);
            for (int x4 = tid; x4 < TI * KK / 4; x4 += THR) {
                float4 a = lg[x4];
                a.x *= cs; a.y *= cs; a.z *= cs; a.w *= cs;
                *(float4*)&lc_s[(x4 >> 6) * KK + (x4 & 63) * 4] = a;
            }
            const float4* rg = (const float4*)(g_right + (b * SS + j0) * KK);
            for (int x4 = tid; x4 < TJ * KK / 4; x4 += THR) {
                float4 a = rg[x4];
                a.x *= cs; a.y *= cs; a.z *= cs; a.w *= cs;
                *(float4*)&rc_s[(x4 >> 6) * RC_STR + (x4 & 63) * 4] = a;
            }
        }
        __syncthreads();

        float acc[NT][4];
#pragma unroll
        for (int n = 0; n < NT; n++) {
            acc[n][0] = 0.f; acc[n][1] = 0.f; acc[n][2] = 0.f; acc[n][3] = 0.f;
        }

        const float* lrow = lc_s + w * KK;
        const float* r0p = rc_s + gp * RC_STR;
        const float* r1p = rc_s + (gp + 8) * RC_STR;

#pragma unroll 2
        for (int ks = 0; ks < KK / 8; ks++) {
            const int k0 = ks * 8;
            const float l0 = lrow[k0 + kq];
            const float l1 = lrow[k0 + kq + 4];
            const uint32_t a0 = tanh_tf32(l0 + r0p[k0 + kq]);
            const uint32_t a1 = tanh_tf32(l0 + r1p[k0 + kq]);
            const uint32_t a2 = tanh_tf32(l1 + r0p[k0 + kq + 4]);
            const uint32_t a3 = tanh_tf32(l1 + r1p[k0 + kq + 4]);

            const uint32_t* vk0 = v_s + (k0 + kq) * 56 + gp;
            const uint32_t* vk1 = vk0 + 4 * 56;
#pragma unroll
            for (int n = 0; n < NT; n++) {
                mma_tf32(acc[n], a0, a1, a2, a3, vk0[8 * n], vk1[8 * n]);
            }
        }

        // Epilogue: D c0,c1 at (row=gp, p=2kq,2kq+1), c2,c3 at row gp+8.
        const int i = i0 + w;
        float* o0 = out + (size_t)((b * SS + i) * SS + j0 + gp) * PP;
        float* o1 = o0 + 8 * PP;
#pragma unroll
        for (int n = 0; n < NT; n++) {
            int p = 8 * n + 2 * kq;
            if (p < PP) {   // only n==6 filters (kq!=0)
                *(float2*)(o0 + p) = make_float2(acc[n][0], acc[n][1]);
                *(float2*)(o1 + p) = make_float2(acc[n][2], acc[n][3]);
            }
        }
    }
}

// ---------------------------------------------------------------------------
// Launch. Inputs (metadata order): x, u_a, w_a, b_s, v. Output: float32.
// ---------------------------------------------------------------------------
extern "C" void kernel_launch(void* const* d_in, const int* in_sizes, int n_in,
                              void* d_out, int out_size)
{
    const float* x   = (const float*)d_in[0];
    const float* u_a = (const float*)d_in[1];
    const float* w_a = (const float*)d_in[2];
    const float* b_s = (const float*)d_in[3];
    const float* v   = (const float*)d_in[4];
    float* out = (float*)d_out;

    cudaFuncSetAttribute(mhs_mma_kernel, cudaFuncAttributeMaxDynamicSharedMemorySize, SM_BYTES);

    dim3 g1(KK / 64, (BS * SS) / 64, 2);
    proj_kernel<<<g1, 256>>>(x, u_a, w_a, b_s);

    mhs_mma_kernel<<<148, THR, SM_BYTES>>>(v, out);
}

// round 7
// speedup vs baseline: 3.7291x; 1.4837x over previous
#include <cuda_runtime.h>
#include <cstdint>

// Problem shape (fixed by dataset)
#define BS 8
#define SS 256
#define HH 768
#define KK 256
#define PP 50

// Scratch: left[b,s,k], right[b,s,k] (b_s folded into right). 2 MB each.
__device__ float g_left[BS * SS * KK];
__device__ float g_right[BS * SS * KK];

// ---------------------------------------------------------------------------
// Helpers
// ---------------------------------------------------------------------------
__device__ __forceinline__ float2 ffma2(const float2 a, const float2 b, const float2 c) {
    float2 r;
    asm("fma.rn.f32x2 %0, %1, %2, %3;"
        : "=l"(reinterpret_cast<unsigned long long &>(r))
        : "l"(reinterpret_cast<const unsigned long long &>(a)),
          "l"(reinterpret_cast<const unsigned long long &>(b)),
          "l"(reinterpret_cast<const unsigned long long &>(c)));
    return r;
}

// Single-MUFU tanh (sm_75+ base ISA).
__device__ __forceinline__ float tanh_hw(float s) {
    float t;
    asm("tanh.approx.f32 %0, %1;" : "=f"(t) : "f"(s));
    return t;
}

// Pack two f32 -> f16x2. PTX: first source goes to UPPER half.
__device__ __forceinline__ uint32_t pack_f16x2(float hi, float lo) {
    uint32_t d;
    asm("cvt.rn.f16x2.f32 %0, %1, %2;" : "=r"(d) : "f"(hi), "f"(lo));
    return d;
}

// tanh both, pack: lo half = tanh(s_lo) (even k), hi half = tanh(s_hi).
__device__ __forceinline__ uint32_t tanh2_f16(float s_lo, float s_hi) {
    return pack_f16x2(tanh_hw(s_hi), tanh_hw(s_lo));
}

// m16n8k16 fp16 MMA with f32 accum (base ISA, sm_80+)
__device__ __forceinline__ void mma_f16(float* c, uint32_t a0, uint32_t a1,
                                        uint32_t a2, uint32_t a3,
                                        uint32_t b0, uint32_t b1) {
    asm volatile("mma.sync.aligned.m16n8k16.row.col.f32.f16.f16.f32 "
                 "{%0,%1,%2,%3}, {%4,%5,%6,%7}, {%8,%9}, {%0,%1,%2,%3};"
                 : "+f"(c[0]), "+f"(c[1]), "+f"(c[2]), "+f"(c[3])
                 : "r"(a0), "r"(a1), "r"(a2), "r"(a3), "r"(b0), "r"(b1));
}

// ---------------------------------------------------------------------------
// Kernel 1: projections. z=0: g_left = x @ u_a ; z=1: g_right = x @ w_a + b_s
// ---------------------------------------------------------------------------
__global__ __launch_bounds__(256) void proj_kernel(
    const float* __restrict__ x, const float* __restrict__ u_a,
    const float* __restrict__ w_a, const float* __restrict__ b_s)
{
    const int zz = blockIdx.z;
    const float* __restrict__ W = zz ? w_a : u_a;
    float* __restrict__ O = zz ? g_right : g_left;
    const int m0 = blockIdx.y * 64;
    const int k0 = blockIdx.x * 64;

    __shared__ float As[16 * 68];
    __shared__ __align__(16) float Bsm[16 * 64];

    const int tid = threadIdx.x;
    const int tx = tid & 15;
    const int ty = tid >> 4;

    float2 acc[4][2];
#pragma unroll
    for (int r = 0; r < 4; r++) {
        acc[r][0] = make_float2(0.f, 0.f);
        acc[r][1] = make_float2(0.f, 0.f);
    }

    for (int h0 = 0; h0 < HH; h0 += 16) {
#pragma unroll
        for (int l = 0; l < 4; l++) {
            int idx = tid + l * 256;
            int mm = idx >> 4, hh = idx & 15;
            As[hh * 68 + mm] = x[(m0 + mm) * HH + h0 + hh];
        }
#pragma unroll
        for (int l = 0; l < 4; l++) {
            int idx = tid + l * 256;
            int hh = idx >> 6, kk = idx & 63;
            Bsm[hh * 64 + kk] = W[(h0 + hh) * KK + k0 + kk];
        }
        __syncthreads();

#pragma unroll
        for (int hh = 0; hh < 16; hh++) {
            float4 b4 = *(const float4*)&Bsm[hh * 64 + tx * 4];
            float2 b0 = make_float2(b4.x, b4.y);
            float2 b1 = make_float2(b4.z, b4.w);
#pragma unroll
            for (int r = 0; r < 4; r++) {
                float a = As[hh * 68 + ty * 4 + r];
                float2 a2 = make_float2(a, a);
                acc[r][0] = ffma2(a2, b0, acc[r][0]);
                acc[r][1] = ffma2(a2, b1, acc[r][1]);
            }
        }
        __syncthreads();
    }

    float2 bs01 = make_float2(0.f, 0.f), bs23 = make_float2(0.f, 0.f);
    if (zz) {
        bs01 = *(const float2*)&b_s[k0 + tx * 4];
        bs23 = *(const float2*)&b_s[k0 + tx * 4 + 2];
    }
#pragma unroll
    for (int r = 0; r < 4; r++) {
        int m = m0 + ty * 4 + r;
        float2 v0 = acc[r][0], v1 = acc[r][1];
        v0.x += bs01.x; v0.y += bs01.y;
        v1.x += bs23.x; v1.y += bs23.y;
        float2* op = (float2*)&O[m * KK + k0 + tx * 4];
        op[0] = v0;
        op[1] = v1;
    }
}

// ---------------------------------------------------------------------------
// Kernel 2: out[b,i,j,p] = sum_k tanh(left[b,i,k]+right[b,j,k]) * v[k,p]
// via mma.sync m16n8k16 fp16 (f32 accum).
//   Tile = 16 i x 16 j. Warp w owns i = i0+w, all 16 j.
//   A (16j x 16k per kstep) = tanh values computed straight into f16x2 frags:
//     a0={t(gp,K0+2kq),t(gp,+1)} a1={t(gp+8,..)} a2={t(gp,K0+2kq+8),+9} a3={t(gp+8,..)}
//   B = v packed fp16x2 pairs: vp[kpair][col], row stride 72 u32
//     -> LDS.32 bank = (8*kq + gp)%32: all 32 lanes distinct, conflict-free.
//   7 n-tiles cover P=50 (pad 56). acc = 7x4 f32.
// 2 CTAs/SM (regs capped 64, smem ~70KB), persistent 296 blocks.
// ---------------------------------------------------------------------------
#define TI 16
#define TJ 16
#define NT 7
#define NTILES 2048             // BS * (SS/TI) * (SS/TJ)
#define THR 512
#define VP_STR 72               // u32 stride per kpair row (72%32==8 -> conflict-free)
#define RC_STR 264              // right smem float stride (264%32==8 -> conflict-free LDS.64)

// Dynamic smem layout (in 4-byte words)
#define SVP 0                              // vp: 128 rows x 72 u32 = 9216 words
#define SL (SVP + (KK / 2) * VP_STR)       // left:  16 x 256 f32   = 4096
#define SR (SL + TI * KK)                  // right: 16 x 264 f32   = 4224
#define SM_WORDS (SR + TJ * RC_STR)
#define SM_BYTES (SM_WORDS * 4)            // ~70 KB

__global__ __launch_bounds__(THR, 2) void mhs_mma_kernel(
    const float* __restrict__ v, float* __restrict__ out)
{
    extern __shared__ float sm[];
    uint32_t* vp = (uint32_t*)(sm + SVP);
    float* lc_s = sm + SL;
    float* rc_s = sm + SR;

    const int tid = threadIdx.x;
    const int w = tid >> 5;
    const int lane = tid & 31;
    const int kq = lane & 3;
    const int gp = lane >> 2;

    // Stage v as packed fp16x2 {lo=v[2kp][c], hi=v[2kp+1][c]}, cols padded to 56.
    for (int idx = tid; idx < (KK / 2) * 56; idx += THR) {
        int kp = idx / 56, c = idx - kp * 56;
        float v0 = (c < PP) ? v[(2 * kp) * PP + c] : 0.0f;
        float v1 = (c < PP) ? v[(2 * kp + 1) * PP + c] : 0.0f;
        vp[kp * VP_STR + c] = pack_f16x2(v1, v0);
    }

    for (int t = blockIdx.x; t < NTILES; t += gridDim.x) {
        const int b = t >> 8;
        const int rem = t & 255;
        const int i0 = (rem >> 4) * TI;
        const int j0 = (rem & 15) * TJ;

        __syncthreads();   // protect lc/rc from laggard readers of previous tile

        // Stage left/right rows (raw f32; tanh.approx takes unscaled arg)
        {
            const float4* lg = (const float4*)(g_left + (b * SS + i0) * KK);
            for (int x4 = tid; x4 < TI * KK / 4; x4 += THR)
                *(float4*)&lc_s[(x4 >> 6) * KK + (x4 & 63) * 4] = lg[x4];
            const float4* rg = (const float4*)(g_right + (b * SS + j0) * KK);
            for (int x4 = tid; x4 < TJ * KK / 4; x4 += THR)
                *(float4*)&rc_s[(x4 >> 6) * RC_STR + (x4 & 63) * 4] = rg[x4];
        }
        __syncthreads();

        float acc[NT][4];
#pragma unroll
        for (int n = 0; n < NT; n++) {
            acc[n][0] = 0.f; acc[n][1] = 0.f; acc[n][2] = 0.f; acc[n][3] = 0.f;
        }

        const float* lrow = lc_s + w * KK;
        const float* r0p = rc_s + gp * RC_STR;
        const float* r1p = rc_s + (gp + 8) * RC_STR;

#pragma unroll 4
        for (int ks = 0; ks < KK / 16; ks++) {
            const int K0 = 16 * ks + 2 * kq;
            // l/r pairs: (K0, K0+1) and (K0+8, K0+9)
            const float2 lA = *(const float2*)(lrow + K0);
            const float2 lB = *(const float2*)(lrow + K0 + 8);
            const float2 r0A = *(const float2*)(r0p + K0);
            const float2 r0B = *(const float2*)(r0p + K0 + 8);
            const float2 r1A = *(const float2*)(r1p + K0);
            const float2 r1B = *(const float2*)(r1p + K0 + 8);

            const uint32_t a0 = tanh2_f16(lA.x + r0A.x, lA.y + r0A.y);
            const uint32_t a1 = tanh2_f16(lA.x + r1A.x, lA.y + r1A.y);
            const uint32_t a2 = tanh2_f16(lB.x + r0B.x, lB.y + r0B.y);
            const uint32_t a3 = tanh2_f16(lB.x + r1B.x, lB.y + r1B.y);

            const uint32_t* v0 = vp + (8 * ks + kq) * VP_STR + gp;
            const uint32_t* v1 = v0 + 4 * VP_STR;
#pragma unroll
            for (int n = 0; n < NT; n++)
                mma_f16(acc[n], a0, a1, a2, a3, v0[8 * n], v1[8 * n]);
        }

        // Epilogue: c0,c1 at (j=gp, p=8n+2kq..+1), c2,c3 at j=gp+8.
        const int i = i0 + w;
        float* o0 = out + (size_t)((b * SS + i) * SS + j0 + gp) * PP;
        float* o1 = o0 + 8 * PP;
#pragma unroll
        for (int n = 0; n < NT; n++) {
            int p = 8 * n + 2 * kq;
            if (p < PP) {   // only n==6 filters (kq!=0)
                *(float2*)(o0 + p) = make_float2(acc[n][0], acc[n][1]);
                *(float2*)(o1 + p) = make_float2(acc[n][2], acc[n][3]);
            }
        }
    }
}

// ---------------------------------------------------------------------------
// Launch. Inputs (metadata order): x, u_a, w_a, b_s, v. Output: float32.
// ---------------------------------------------------------------------------
extern "C" void kernel_launch(void* const* d_in, const int* in_sizes, int n_in,
                              void* d_out, int out_size)
{
    const float* x   = (const float*)d_in[0];
    const float* u_a = (const float*)d_in[1];
    const float* w_a = (const float*)d_in[2];
    const float* b_s = (const float*)d_in[3];
    const float* v   = (const float*)d_in[4];
    float* out = (float*)d_out;

    cudaFuncSetAttribute(mhs_mma_kernel, cudaFuncAttributeMaxDynamicSharedMemorySize, SM_BYTES);

    dim3 g1(KK / 64, (BS * SS) / 64, 2);
    proj_kernel<<<g1, 256>>>(x, u_a, w_a, b_s);

    mhs_mma_kernel<<<296, THR, SM_BYTES>>>(v, out);
}

// round 10
// speedup vs baseline: 4.0886x; 1.0964x over previous
#include <cuda_runtime.h>
#include <cuda_fp16.h>
#include <cstdint>

// Problem shape (fixed by dataset)
#define BS 8
#define SS 256
#define HH 768
#define KK 256
#define PP 50

// Scratch: left/right as fp16 (b_s folded into right). 1 MB each.
__device__ __half g_left_h[BS * SS * KK];
__device__ __half g_right_h[BS * SS * KK];

// ---------------------------------------------------------------------------
// Helpers
// ---------------------------------------------------------------------------
__device__ __forceinline__ float2 ffma2(const float2 a, const float2 b, const float2 c) {
    float2 r;
    asm("fma.rn.f32x2 %0, %1, %2, %3;"
        : "=l"(reinterpret_cast<unsigned long long &>(r))
        : "l"(reinterpret_cast<const unsigned long long &>(a)),
          "l"(reinterpret_cast<const unsigned long long &>(b)),
          "l"(reinterpret_cast<const unsigned long long &>(c)));
    return r;
}

// Pack two f32 -> f16x2; first operand lands in UPPER 16 bits.
__device__ __forceinline__ uint32_t pack_f16x2(float hi, float lo) {
    uint32_t d;
    asm("cvt.rn.f16x2.f32 %0, %1, %2;" : "=r"(d) : "f"(hi), "f"(lo));
    return d;
}

__device__ __forceinline__ uint32_t hadd2(uint32_t a, uint32_t b) {
    uint32_t d;
    asm("add.rn.f16x2 %0, %1, %2;" : "=r"(d) : "r"(a), "r"(b));
    return d;
}

// Packed fp16 tanh: one MUFU for two values (sm_75+ base ISA).
__device__ __forceinline__ uint32_t tanh2h(uint32_t s) {
    uint32_t d;
    asm("tanh.approx.f16x2 %0, %1;" : "=r"(d) : "r"(s));
    return d;
}

// m16n8k16 fp16 MMA with f32 accum (base ISA, sm_80+)
__device__ __forceinline__ void mma_f16(float* c, uint32_t a0, uint32_t a1,
                                        uint32_t a2, uint32_t a3,
                                        uint32_t b0, uint32_t b1) {
    asm volatile("mma.sync.aligned.m16n8k16.row.col.f32.f16.f16.f32 "
                 "{%0,%1,%2,%3}, {%4,%5,%6,%7}, {%8,%9}, {%0,%1,%2,%3};"
                 : "+f"(c[0]), "+f"(c[1]), "+f"(c[2]), "+f"(c[3])
                 : "r"(a0), "r"(a1), "r"(a2), "r"(a3), "r"(b0), "r"(b1));
}

// ---------------------------------------------------------------------------
// Kernel 1: projections. z=0: g_left_h = x @ u_a ; z=1: g_right_h = x @ w_a + b_s
// fp32 compute, fp16 store.
// ---------------------------------------------------------------------------
__global__ __launch_bounds__(256) void proj_kernel(
    const float* __restrict__ x, const float* __restrict__ u_a,
    const float* __restrict__ w_a, const float* __restrict__ b_s)
{
    const int zz = blockIdx.z;
    const float* __restrict__ W = zz ? w_a : u_a;
    __half* __restrict__ O = zz ? g_right_h : g_left_h;
    const int m0 = blockIdx.y * 64;
    const int k0 = blockIdx.x * 64;

    __shared__ float As[16 * 68];
    __shared__ __align__(16) float Bsm[16 * 64];

    const int tid = threadIdx.x;
    const int tx = tid & 15;
    const int ty = tid >> 4;

    float2 acc[4][2];
#pragma unroll
    for (int r = 0; r < 4; r++) {
        acc[r][0] = make_float2(0.f, 0.f);
        acc[r][1] = make_float2(0.f, 0.f);
    }

    for (int h0 = 0; h0 < HH; h0 += 16) {
#pragma unroll
        for (int l = 0; l < 4; l++) {
            int idx = tid + l * 256;
            int mm = idx >> 4, hh = idx & 15;
            As[hh * 68 + mm] = x[(m0 + mm) * HH + h0 + hh];
        }
#pragma unroll
        for (int l = 0; l < 4; l++) {
            int idx = tid + l * 256;
            int hh = idx >> 6, kk = idx & 63;
            Bsm[hh * 64 + kk] = W[(h0 + hh) * KK + k0 + kk];
        }
        __syncthreads();

#pragma unroll
        for (int hh = 0; hh < 16; hh++) {
            float4 b4 = *(const float4*)&Bsm[hh * 64 + tx * 4];
            float2 b0 = make_float2(b4.x, b4.y);
            float2 b1 = make_float2(b4.z, b4.w);
#pragma unroll
            for (int r = 0; r < 4; r++) {
                float a = As[hh * 68 + ty * 4 + r];
                float2 a2 = make_float2(a, a);
                acc[r][0] = ffma2(a2, b0, acc[r][0]);
                acc[r][1] = ffma2(a2, b1, acc[r][1]);
            }
        }
        __syncthreads();
    }

    float2 bs01 = make_float2(0.f, 0.f), bs23 = make_float2(0.f, 0.f);
    if (zz) {
        bs01 = *(const float2*)&b_s[k0 + tx * 4];
        bs23 = *(const float2*)&b_s[k0 + tx * 4 + 2];
    }
#pragma unroll
    for (int r = 0; r < 4; r++) {
        int m = m0 + ty * 4 + r;
        float2 v0 = acc[r][0], v1 = acc[r][1];
        v0.x += bs01.x; v0.y += bs01.y;
        v1.x += bs23.x; v1.y += bs23.y;
        // pack 4 f32 -> 2 f16x2, one 8B store (lo half = even k)
        uint2 pk;
        pk.x = pack_f16x2(v0.y, v0.x);
        pk.y = pack_f16x2(v1.y, v1.x);
        *(uint2*)&O[m * KK + k0 + tx * 4] = pk;
    }
}

// ---------------------------------------------------------------------------
// Kernel 2: out[b,i,j,p] = sum_k tanh(left[b,i,k]+right[b,j,k]) * v[k,p]
// mma.sync m16n8k16 fp16. Warp w owns i=i0+w, 16 j.
// l/r staged as fp16 via plain LDG->STS (R7-style, 2 syncs/tile).
// tanh fragments: a = tanh.approx.f16x2(add.rn.f16x2(l_pair, r_pair)).
// B = v fp16x2, stride 72 u32 (conflict-free). acc 7x4 f32.
// ---------------------------------------------------------------------------
#define TI 16
#define TJ 16
#define NT 7
#define NTILES 2048
#define THR 512
#define VP_STR 72      // u32/row for vp  (72%32==8 -> banks 8kq+gp distinct)
#define HSTR 132       // u32/row for l/r (132%32==4 -> banks 4gp+kq distinct)

// smem layout in u32 words
#define SVP 0                               // vp: 128 x 72          = 9216
#define SLH (SVP + (KK / 2) * VP_STR)       // l:  16 x 132          = 2112
#define SRH (SLH + TI * HSTR)               // r:  16 x 132          = 2112
#define SM_WORDS (SRH + TJ * HSTR)
#define SM_BYTES (SM_WORDS * 4)             // 53760 B

__global__ __launch_bounds__(THR, 2) void mhs_mma_kernel(
    const float* __restrict__ v, float* __restrict__ out)
{
    extern __shared__ float sm[];
    uint32_t* smw = (uint32_t*)sm;
    uint32_t* vp = smw + SVP;

    const int tid = threadIdx.x;
    const int w = tid >> 5;
    const int lane = tid & 31;
    const int kq = lane & 3;
    const int gp = lane >> 2;

    // Stage v as packed fp16x2 {lo=v[2kp][c], hi=v[2kp+1][c]}, cols padded to 56.
    for (int idx = tid; idx < (KK / 2) * 56; idx += THR) {
        int kp = idx / 56, c = idx - kp * 56;
        float v0 = (c < PP) ? v[(2 * kp) * PP + c] : 0.0f;
        float v1 = (c < PP) ? v[(2 * kp + 1) * PP + c] : 0.0f;
        vp[kp * VP_STR + c] = pack_f16x2(v1, v0);
    }

    for (int t = blockIdx.x; t < NTILES; t += gridDim.x) {
        const int b = t >> 8;
        const int rem = t & 255;
        const int i0 = (rem >> 4) * TI;
        const int j0 = (rem & 15) * TJ;

        __syncthreads();   // all warps done reading previous tile's l/r

        // Stage l/r tiles: 16 rows x 256 fp16 = 16 rows x 4 uint4 chunks each.
        {
            const uint4* lg = (const uint4*)(g_left_h + (b * SS + i0) * KK);
            const uint4* rg = (const uint4*)(g_right_h + (b * SS + j0) * KK);
            const int row = tid >> 5, ch = tid & 31;   // 16 rows x 32 chunks of 16B
            // each row has 256*2/16 = 32 chunks; one chunk per thread
            *(uint4*)(smw + SLH + row * HSTR + ch * 4) = lg[row * 32 + ch];
            *(uint4*)(smw + SRH + row * HSTR + ch * 4) = rg[row * 32 + ch];
        }
        __syncthreads();

        const uint32_t* lw = smw + SLH + w * HSTR;
        const uint32_t* r0w = smw + SRH + gp * HSTR;
        const uint32_t* r1w = r0w + 8 * HSTR;

        float acc[NT][4];
#pragma unroll
        for (int n = 0; n < NT; n++) {
            acc[n][0] = 0.f; acc[n][1] = 0.f; acc[n][2] = 0.f; acc[n][3] = 0.f;
        }

#pragma unroll 4
        for (int ks = 0; ks < KK / 16; ks++) {
            const int wA = 8 * ks + kq;        // word = k-pair (K0,K0+1)
            const int wB = wA + 4;             // word = k-pair (K0+8,K0+9)
            const uint32_t lA = lw[wA], lB = lw[wB];
            const uint32_t a0 = tanh2h(hadd2(lA, r0w[wA]));
            const uint32_t a1 = tanh2h(hadd2(lA, r1w[wA]));
            const uint32_t a2 = tanh2h(hadd2(lB, r0w[wB]));
            const uint32_t a3 = tanh2h(hadd2(lB, r1w[wB]));

            const uint32_t* v0 = vp + wA * VP_STR + gp;
            const uint32_t* v1 = v0 + 4 * VP_STR;
#pragma unroll
            for (int n = 0; n < NT; n++)
                mma_f16(acc[n], a0, a1, a2, a3, v0[8 * n], v1[8 * n]);
        }

        // Epilogue: c0,c1 at (j=gp, p=8n+2kq), c2,c3 at j=gp+8.
        const int i = i0 + w;
        float* o0 = out + (size_t)((b * SS + i) * SS + j0 + gp) * PP;
        float* o1 = o0 + 8 * PP;
#pragma unroll
        for (int n = 0; n < NT; n++) {
            int p = 8 * n + 2 * kq;
            if (p < PP) {
                *(float2*)(o0 + p) = make_float2(acc[n][0], acc[n][1]);
                *(float2*)(o1 + p) = make_float2(acc[n][2], acc[n][3]);
            }
        }
    }
}

// ---------------------------------------------------------------------------
// Launch. Inputs (metadata order): x, u_a, w_a, b_s, v. Output: float32.
// ---------------------------------------------------------------------------
extern "C" void kernel_launch(void* const* d_in, const int* in_sizes, int n_in,
                              void* d_out, int out_size)
{
    const float* x   = (const float*)d_in[0];
    const float* u_a = (const float*)d_in[1];
    const float* w_a = (const float*)d_in[2];
    const float* b_s = (const float*)d_in[3];
    const float* v   = (const float*)d_in[4];
    float* out = (float*)d_out;

    cudaFuncSetAttribute(mhs_mma_kernel, cudaFuncAttributeMaxDynamicSharedMemorySize, SM_BYTES);

    dim3 g1(KK / 64, (BS * SS) / 64, 2);
    proj_kernel<<<g1, 256>>>(x, u_a, w_a, b_s);

    mhs_mma_kernel<<<296, THR, SM_BYTES>>>(v, out);
}

// round 11
// speedup vs baseline: 5.6647x; 1.3855x over previous
#include <cuda_runtime.h>
#include <cuda_fp16.h>
#include <cstdint>

// Problem shape (fixed by dataset)
#define BS 8
#define SS 256
#define HH 768
#define KK 256
#define PP 50

// Scratch: left/right as fp16 (b_s folded into right). 1 MB each.
__device__ __half g_left_h[BS * SS * KK];
__device__ __half g_right_h[BS * SS * KK];

// ---------------------------------------------------------------------------
// Helpers
// ---------------------------------------------------------------------------
// Pack two f32 -> f16x2; first operand lands in UPPER 16 bits.
__device__ __forceinline__ uint32_t pack_f16x2(float hi, float lo) {
    uint32_t d;
    asm("cvt.rn.f16x2.f32 %0, %1, %2;" : "=r"(d) : "f"(hi), "f"(lo));
    return d;
}

__device__ __forceinline__ uint32_t hadd2(uint32_t a, uint32_t b) {
    uint32_t d;
    asm("add.rn.f16x2 %0, %1, %2;" : "=r"(d) : "r"(a), "r"(b));
    return d;
}

// Packed fp16 tanh: one MUFU for two values (sm_75+ base ISA).
__device__ __forceinline__ uint32_t tanh2h(uint32_t s) {
    uint32_t d;
    asm("tanh.approx.f16x2 %0, %1;" : "=r"(d) : "r"(s));
    return d;
}

// m16n8k16 fp16 MMA with f32 accum (base ISA, sm_80+)
__device__ __forceinline__ void mma_f16(float* c, uint32_t a0, uint32_t a1,
                                        uint32_t a2, uint32_t a3,
                                        uint32_t b0, uint32_t b1) {
    asm volatile("mma.sync.aligned.m16n8k16.row.col.f32.f16.f16.f32 "
                 "{%0,%1,%2,%3}, {%4,%5,%6,%7}, {%8,%9}, {%0,%1,%2,%3};"
                 : "+f"(c[0]), "+f"(c[1]), "+f"(c[2]), "+f"(c[3])
                 : "r"(a0), "r"(a1), "r"(a2), "r"(a3), "r"(b0), "r"(b1));
}

// m16n8k8 tf32 MMA with f32 accum (base ISA, sm_80+). Operands are raw f32
// bits; hardware truncates mantissa to tf32.
__device__ __forceinline__ void mma_tf32(float* c, uint32_t a0, uint32_t a1,
                                         uint32_t a2, uint32_t a3,
                                         uint32_t b0, uint32_t b1) {
    asm volatile("mma.sync.aligned.m16n8k8.row.col.f32.tf32.tf32.f32 "
                 "{%0,%1,%2,%3}, {%4,%5,%6,%7}, {%8,%9}, {%0,%1,%2,%3};"
                 : "+f"(c[0]), "+f"(c[1]), "+f"(c[2]), "+f"(c[3])
                 : "r"(a0), "r"(a1), "r"(a2), "r"(a3), "r"(b0), "r"(b1));
}

__device__ __forceinline__ uint32_t smem_u32(const void* p) {
    uint32_t a;
    asm("{ .reg .u64 t; cvta.to.shared.u64 t, %1; cvt.u32.u64 %0, t; }" : "=r"(a) : "l"(p));
    return a;
}

__device__ __forceinline__ void cp_async16(uint32_t smem_dst, const void* gsrc) {
    asm volatile("cp.async.cg.shared.global [%0], [%1], 16;" :: "r"(smem_dst), "l"(gsrc));
}
#define CP_COMMIT()  asm volatile("cp.async.commit_group;" ::: "memory")
#define CP_WAIT0()   asm volatile("cp.async.wait_group 0;" ::: "memory")

// ---------------------------------------------------------------------------
// Kernel 1 (tensor core): projections via mma.sync tf32 m16n8k8.
// z=0: g_left_h = x @ u_a ; z=1: g_right_h = x @ w_a + b_s (fp16 store)
// Block 128 thr (4 warps 2x2), block tile 64m x 64n, warp tile 32x32.
// K=768 chunked by 32, cp.async double-buffered.
// ---------------------------------------------------------------------------
#define PK 32                       // k chunk
#define NCH (HH / PK)               // 24 chunks
#define XSTR 36                     // x smem row stride (words): banks 4gp+kq
#define WSTR 72                     // W smem row stride (words): banks 8kq+gp
#define XS_W (64 * XSTR)            // 2304 words per buffer
#define WS_W (PK * WSTR)            // 2304 words per buffer
#define PSM_WORDS (2 * XS_W + 2 * WS_W)
#define PSM_BYTES (PSM_WORDS * 4)   // 36864 B

__global__ __launch_bounds__(128, 2) void proj_mma_kernel(
    const float* __restrict__ x, const float* __restrict__ u_a,
    const float* __restrict__ w_a, const float* __restrict__ b_s)
{
    extern __shared__ float psm[];
    uint32_t* smw = (uint32_t*)psm;
    const uint32_t sb = smem_u32(smw);

    const int zz = blockIdx.z;
    const float* __restrict__ W = zz ? w_a : u_a;
    __half* __restrict__ O = zz ? g_right_h : g_left_h;
    const int m0 = blockIdx.y * 64;
    const int n0 = blockIdx.x * 64;

    const int tid = threadIdx.x;
    const int w = tid >> 5;
    const int lane = tid & 31;
    const int kq = lane & 3;
    const int gp = lane >> 2;
    const int wm = (w >> 1) * 32;   // warp m offset in block tile
    const int wn = (w & 1) * 32;    // warp n offset in block tile

    // stage chunk c into buffer buf: x tile 64x32 f32, W tile 32x64 f32
    auto stage = [&](int c, int buf) {
        const int h0 = c * PK;
        // x: 512 uint4 (64 rows x 8 chunks)
#pragma unroll
        for (int q = 0; q < 4; q++) {
            int idx = tid + q * 128;
            int row = idx >> 3, c4 = idx & 7;
            cp_async16(sb + (buf * XS_W + row * XSTR + c4 * 4) * 4,
                       x + (size_t)(m0 + row) * HH + h0 + c4 * 4);
        }
        // W: 512 uint4 (32 rows x 16 chunks)
#pragma unroll
        for (int q = 0; q < 4; q++) {
            int idx = tid + q * 128;
            int row = idx >> 4, c4 = idx & 15;
            cp_async16(sb + (2 * XS_W + buf * WS_W + row * WSTR + c4 * 4) * 4,
                       W + (size_t)(h0 + row) * KK + n0 + c4 * 4);
        }
        CP_COMMIT();
    };

    float acc[2][4][4];
#pragma unroll
    for (int mt = 0; mt < 2; mt++)
#pragma unroll
        for (int nt = 0; nt < 4; nt++)
#pragma unroll
            for (int e = 0; e < 4; e++) acc[mt][nt][e] = 0.f;

    stage(0, 0);

    for (int c = 0; c < NCH; c++) {
        const int buf = c & 1;
        CP_WAIT0();
        __syncthreads();             // buf ready; all warps done with prev compute
        if (c + 1 < NCH) stage(c + 1, buf ^ 1);

        const uint32_t* xs = smw + buf * XS_W;
        const uint32_t* ws = smw + 2 * XS_W + buf * WS_W;

#pragma unroll
        for (int ks = 0; ks < PK / 8; ks++) {
            const int k0 = ks * 8;
            uint32_t a[2][4];
#pragma unroll
            for (int mt = 0; mt < 2; mt++) {
                const uint32_t* xr = xs + (wm + mt * 16 + gp) * XSTR + k0 + kq;
                a[mt][0] = xr[0];
                a[mt][1] = xr[8 * XSTR];
                a[mt][2] = xr[4];
                a[mt][3] = xr[8 * XSTR + 4];
            }
#pragma unroll
            for (int nt = 0; nt < 4; nt++) {
                const uint32_t* wr = ws + (k0 + kq) * WSTR + wn + nt * 8 + gp;
                uint32_t b0 = wr[0];
                uint32_t b1 = wr[4 * WSTR];
#pragma unroll
                for (int mt = 0; mt < 2; mt++)
                    mma_tf32(acc[mt][nt], a[mt][0], a[mt][1], a[mt][2], a[mt][3], b0, b1);
            }
        }
    }
    __syncthreads();

    // Epilogue: c0,c1 at (row=gp, n=nt*8+2kq), c2,c3 at row gp+8. Pack -> fp16.
#pragma unroll
    for (int mt = 0; mt < 2; mt++) {
        const int m = m0 + wm + mt * 16 + gp;
#pragma unroll
        for (int nt = 0; nt < 4; nt++) {
            const int n = n0 + wn + nt * 8 + 2 * kq;
            float bx = 0.f, by = 0.f;
            if (zz) {
                float2 bsv = *(const float2*)&b_s[n];
                bx = bsv.x; by = bsv.y;
            }
            *(uint32_t*)&O[(size_t)m * KK + n] =
                pack_f16x2(acc[mt][nt][1] + by, acc[mt][nt][0] + bx);
            *(uint32_t*)&O[(size_t)(m + 8) * KK + n] =
                pack_f16x2(acc[mt][nt][3] + by, acc[mt][nt][2] + bx);
        }
    }
}

// ---------------------------------------------------------------------------
// Kernel 2 (UNCHANGED from R10): out[b,i,j,p] = sum_k tanh(l+r) * v[k,p]
// mma.sync m16n8k16 fp16. Warp w owns i=i0+w, 16 j. LDG->STS staging.
// ---------------------------------------------------------------------------
#define TI 16
#define TJ 16
#define NT 7
#define NTILES 2048
#define THR 512
#define VP_STR 72      // u32/row for vp  (72%32==8 -> banks 8kq+gp distinct)
#define HSTR 132       // u32/row for l/r (132%32==4 -> banks 4gp+kq distinct)

#define SVP 0                               // vp: 128 x 72          = 9216
#define SLH (SVP + (KK / 2) * VP_STR)       // l:  16 x 132          = 2112
#define SRH (SLH + TI * HSTR)               // r:  16 x 132          = 2112
#define SM_WORDS (SRH + TJ * HSTR)
#define SM_BYTES (SM_WORDS * 4)             // 53760 B

__global__ __launch_bounds__(THR, 2) void mhs_mma_kernel(
    const float* __restrict__ v, float* __restrict__ out)
{
    extern __shared__ float sm[];
    uint32_t* smw = (uint32_t*)sm;
    uint32_t* vp = smw + SVP;

    const int tid = threadIdx.x;
    const int w = tid >> 5;
    const int lane = tid & 31;
    const int kq = lane & 3;
    const int gp = lane >> 2;

    // Stage v as packed fp16x2 {lo=v[2kp][c], hi=v[2kp+1][c]}, cols padded to 56.
    for (int idx = tid; idx < (KK / 2) * 56; idx += THR) {
        int kp = idx / 56, c = idx - kp * 56;
        float v0 = (c < PP) ? v[(2 * kp) * PP + c] : 0.0f;
        float v1 = (c < PP) ? v[(2 * kp + 1) * PP + c] : 0.0f;
        vp[kp * VP_STR + c] = pack_f16x2(v1, v0);
    }

    for (int t = blockIdx.x; t < NTILES; t += gridDim.x) {
        const int b = t >> 8;
        const int rem = t & 255;
        const int i0 = (rem >> 4) * TI;
        const int j0 = (rem & 15) * TJ;

        __syncthreads();   // all warps done reading previous tile's l/r

        {
            const uint4* lg = (const uint4*)(g_left_h + (b * SS + i0) * KK);
            const uint4* rg = (const uint4*)(g_right_h + (b * SS + j0) * KK);
            const int row = tid >> 5, ch = tid & 31;   // 16 rows x 32 chunks of 16B
            *(uint4*)(smw + SLH + row * HSTR + ch * 4) = lg[row * 32 + ch];
            *(uint4*)(smw + SRH + row * HSTR + ch * 4) = rg[row * 32 + ch];
        }
        __syncthreads();

        const uint32_t* lw = smw + SLH + w * HSTR;
        const uint32_t* r0w = smw + SRH + gp * HSTR;
        const uint32_t* r1w = r0w + 8 * HSTR;

        float acc[NT][4];
#pragma unroll
        for (int n = 0; n < NT; n++) {
            acc[n][0] = 0.f; acc[n][1] = 0.f; acc[n][2] = 0.f; acc[n][3] = 0.f;
        }

#pragma unroll 4
        for (int ks = 0; ks < KK / 16; ks++) {
            const int wA = 8 * ks + kq;
            const int wB = wA + 4;
            const uint32_t lA = lw[wA], lB = lw[wB];
            const uint32_t a0 = tanh2h(hadd2(lA, r0w[wA]));
            const uint32_t a1 = tanh2h(hadd2(lA, r1w[wA]));
            const uint32_t a2 = tanh2h(hadd2(lB, r0w[wB]));
            const uint32_t a3 = tanh2h(hadd2(lB, r1w[wB]));

            const uint32_t* v0 = vp + wA * VP_STR + gp;
            const uint32_t* v1 = v0 + 4 * VP_STR;
#pragma unroll
            for (int n = 0; n < NT; n++)
                mma_f16(acc[n], a0, a1, a2, a3, v0[8 * n], v1[8 * n]);
        }

        const int i = i0 + w;
        float* o0 = out + (size_t)((b * SS + i) * SS + j0 + gp) * PP;
        float* o1 = o0 + 8 * PP;
#pragma unroll
        for (int n = 0; n < NT; n++) {
            int p = 8 * n + 2 * kq;
            if (p < PP) {
                *(float2*)(o0 + p) = make_float2(acc[n][0], acc[n][1]);
                *(float2*)(o1 + p) = make_float2(acc[n][2], acc[n][3]);
            }
        }
    }
}

// ---------------------------------------------------------------------------
// Launch. Inputs (metadata order): x, u_a, w_a, b_s, v. Output: float32.
// ---------------------------------------------------------------------------
extern "C" void kernel_launch(void* const* d_in, const int* in_sizes, int n_in,
                              void* d_out, int out_size)
{
    const float* x   = (const float*)d_in[0];
    const float* u_a = (const float*)d_in[1];
    const float* w_a = (const float*)d_in[2];
    const float* b_s = (const float*)d_in[3];
    const float* v   = (const float*)d_in[4];
    float* out = (float*)d_out;

    cudaFuncSetAttribute(proj_mma_kernel, cudaFuncAttributeMaxDynamicSharedMemorySize, PSM_BYTES);
    cudaFuncSetAttribute(mhs_mma_kernel, cudaFuncAttributeMaxDynamicSharedMemorySize, SM_BYTES);

    dim3 g1(KK / 64, (BS * SS) / 64, 2);
    proj_mma_kernel<<<g1, 128, PSM_BYTES>>>(x, u_a, w_a, b_s);

    mhs_mma_kernel<<<296, THR, SM_BYTES>>>(v, out);
}

// round 12
// speedup vs baseline: 6.0628x; 1.0703x over previous
#include <cuda_runtime.h>
#include <cuda_fp16.h>
#include <cstdint>

// Problem shape (fixed by dataset)
#define BS 8
#define SS 256
#define HH 768
#define KK 256
#define PP 50

// Scratch: left/right as fp16 (b_s folded into right). 1 MB each.
__device__ __half g_left_h[BS * SS * KK];
__device__ __half g_right_h[BS * SS * KK];

// ---------------------------------------------------------------------------
// Helpers
// ---------------------------------------------------------------------------
// Pack two f32 -> f16x2; first operand lands in UPPER 16 bits.
__device__ __forceinline__ uint32_t pack_f16x2(float hi, float lo) {
    uint32_t d;
    asm("cvt.rn.f16x2.f32 %0, %1, %2;" : "=r"(d) : "f"(hi), "f"(lo));
    return d;
}

__device__ __forceinline__ uint32_t hadd2(uint32_t a, uint32_t b) {
    uint32_t d;
    asm("add.rn.f16x2 %0, %1, %2;" : "=r"(d) : "r"(a), "r"(b));
    return d;
}

// Packed fp16 tanh: one MUFU for two values (sm_75+ base ISA).
__device__ __forceinline__ uint32_t tanh2h(uint32_t s) {
    uint32_t d;
    asm("tanh.approx.f16x2 %0, %1;" : "=r"(d) : "r"(s));
    return d;
}

// Round-to-nearest tf32 (removes the RZ truncation bias of raw-f32 mma operands).
__device__ __forceinline__ uint32_t f2tf32_rna(uint32_t raw) {
    uint32_t r;
    asm("cvt.rna.tf32.f32 %0, %1;" : "=r"(r) : "f"(__uint_as_float(raw)));
    return r;
}

// m16n8k16 fp16 MMA with f32 accum (base ISA, sm_80+)
__device__ __forceinline__ void mma_f16(float* c, uint32_t a0, uint32_t a1,
                                        uint32_t a2, uint32_t a3,
                                        uint32_t b0, uint32_t b1) {
    asm volatile("mma.sync.aligned.m16n8k16.row.col.f32.f16.f16.f32 "
                 "{%0,%1,%2,%3}, {%4,%5,%6,%7}, {%8,%9}, {%0,%1,%2,%3};"
                 : "+f"(c[0]), "+f"(c[1]), "+f"(c[2]), "+f"(c[3])
                 : "r"(a0), "r"(a1), "r"(a2), "r"(a3), "r"(b0), "r"(b1));
}

// m16n8k8 tf32 MMA with f32 accum (base ISA, sm_80+)
__device__ __forceinline__ void mma_tf32(float* c, uint32_t a0, uint32_t a1,
                                         uint32_t a2, uint32_t a3,
                                         uint32_t b0, uint32_t b1) {
    asm volatile("mma.sync.aligned.m16n8k8.row.col.f32.tf32.tf32.f32 "
                 "{%0,%1,%2,%3}, {%4,%5,%6,%7}, {%8,%9}, {%0,%1,%2,%3};"
                 : "+f"(c[0]), "+f"(c[1]), "+f"(c[2]), "+f"(c[3])
                 : "r"(a0), "r"(a1), "r"(a2), "r"(a3), "r"(b0), "r"(b1));
}

__device__ __forceinline__ uint32_t smem_u32(const void* p) {
    uint32_t a;
    asm("{ .reg .u64 t; cvta.to.shared.u64 t, %1; cvt.u32.u64 %0, t; }" : "=r"(a) : "l"(p));
    return a;
}

__device__ __forceinline__ void cp_async16(uint32_t smem_dst, const void* gsrc) {
    asm volatile("cp.async.cg.shared.global [%0], [%1], 16;" :: "r"(smem_dst), "l"(gsrc));
}
#define CP_COMMIT()  asm volatile("cp.async.commit_group;" ::: "memory")
#define CP_WAIT0()   asm volatile("cp.async.wait_group 0;" ::: "memory")

// ---------------------------------------------------------------------------
// Kernel 1 (tensor core): projections via mma.sync tf32 m16n8k8, rna-rounded
// operands. z=0: g_left_h = x @ u_a ; z=1: g_right_h = x @ w_a + b_s
// Block 128 thr (4 warps 2x2), block tile 64m x 64n, warp tile 32x32.
// K=768 chunked by 32, cp.async double-buffered.
// ---------------------------------------------------------------------------
#define PK 32
#define NCH (HH / PK)
#define XSTR 36
#define WSTR 72
#define XS_W (64 * XSTR)
#define WS_W (PK * WSTR)
#define PSM_WORDS (2 * XS_W + 2 * WS_W)
#define PSM_BYTES (PSM_WORDS * 4)   // 36864 B

__global__ __launch_bounds__(128, 2) void proj_mma_kernel(
    const float* __restrict__ x, const float* __restrict__ u_a,
    const float* __restrict__ w_a, const float* __restrict__ b_s)
{
    extern __shared__ float psm[];
    uint32_t* smw = (uint32_t*)psm;
    const uint32_t sb = smem_u32(smw);

    const int zz = blockIdx.z;
    const float* __restrict__ W = zz ? w_a : u_a;
    __half* __restrict__ O = zz ? g_right_h : g_left_h;
    const int m0 = blockIdx.y * 64;
    const int n0 = blockIdx.x * 64;

    const int tid = threadIdx.x;
    const int w = tid >> 5;
    const int lane = tid & 31;
    const int kq = lane & 3;
    const int gp = lane >> 2;
    const int wm = (w >> 1) * 32;
    const int wn = (w & 1) * 32;

    auto stage = [&](int c, int buf) {
        const int h0 = c * PK;
#pragma unroll
        for (int q = 0; q < 4; q++) {
            int idx = tid + q * 128;
            int row = idx >> 3, c4 = idx & 7;
            cp_async16(sb + (buf * XS_W + row * XSTR + c4 * 4) * 4,
                       x + (size_t)(m0 + row) * HH + h0 + c4 * 4);
        }
#pragma unroll
        for (int q = 0; q < 4; q++) {
            int idx = tid + q * 128;
            int row = idx >> 4, c4 = idx & 15;
            cp_async16(sb + (2 * XS_W + buf * WS_W + row * WSTR + c4 * 4) * 4,
                       W + (size_t)(h0 + row) * KK + n0 + c4 * 4);
        }
        CP_COMMIT();
    };

    float acc[2][4][4];
#pragma unroll
    for (int mt = 0; mt < 2; mt++)
#pragma unroll
        for (int nt = 0; nt < 4; nt++)
#pragma unroll
            for (int e = 0; e < 4; e++) acc[mt][nt][e] = 0.f;

    stage(0, 0);

    for (int c = 0; c < NCH; c++) {
        const int buf = c & 1;
        CP_WAIT0();
        __syncthreads();
        if (c + 1 < NCH) stage(c + 1, buf ^ 1);

        const uint32_t* xs = smw + buf * XS_W;
        const uint32_t* ws = smw + 2 * XS_W + buf * WS_W;

#pragma unroll
        for (int ks = 0; ks < PK / 8; ks++) {
            const int k0 = ks * 8;
            uint32_t a[2][4];
#pragma unroll
            for (int mt = 0; mt < 2; mt++) {
                const uint32_t* xr = xs + (wm + mt * 16 + gp) * XSTR + k0 + kq;
                a[mt][0] = f2tf32_rna(xr[0]);
                a[mt][1] = f2tf32_rna(xr[8 * XSTR]);
                a[mt][2] = f2tf32_rna(xr[4]);
                a[mt][3] = f2tf32_rna(xr[8 * XSTR + 4]);
            }
#pragma unroll
            for (int nt = 0; nt < 4; nt++) {
                const uint32_t* wr = ws + (k0 + kq) * WSTR + wn + nt * 8 + gp;
                uint32_t b0 = f2tf32_rna(wr[0]);
                uint32_t b1 = f2tf32_rna(wr[4 * WSTR]);
#pragma unroll
                for (int mt = 0; mt < 2; mt++)
                    mma_tf32(acc[mt][nt], a[mt][0], a[mt][1], a[mt][2], a[mt][3], b0, b1);
            }
        }
    }
    __syncthreads();

#pragma unroll
    for (int mt = 0; mt < 2; mt++) {
        const int m = m0 + wm + mt * 16 + gp;
#pragma unroll
        for (int nt = 0; nt < 4; nt++) {
            const int n = n0 + wn + nt * 8 + 2 * kq;
            float bx = 0.f, by = 0.f;
            if (zz) {
                float2 bsv = *(const float2*)&b_s[n];
                bx = bsv.x; by = bsv.y;
            }
            *(uint32_t*)&O[(size_t)m * KK + n] =
                pack_f16x2(acc[mt][nt][1] + by, acc[mt][nt][0] + bx);
            *(uint32_t*)&O[(size_t)(m + 8) * KK + n] =
                pack_f16x2(acc[mt][nt][3] + by, acc[mt][nt][2] + bx);
        }
    }
}

// ---------------------------------------------------------------------------
// Kernel 2: out[b,i,j,p] = sum_k tanh(l+r) * v[k,p], mma m16n8k16 fp16.
// RESTRUCTURED: 256 thr / 8 warps per CTA; warp w owns TWO i rows
// (i0+2w, i0+2w+1) and shares the v/r fragment loads between them ->
// crossbar bytes per unit work drop 40% (22 vs 40 LDS.32 per 2-i k-step).
// ---------------------------------------------------------------------------
#define TI 16
#define TJ 16
#define NT 7
#define NTILES 2048
#define THR 256
#define VP_STR 72      // u32/row for vp  (banks 8kq+gp distinct)
#define HSTR 132       // u32/row for l/r (banks 4gp+kq distinct)

#define SVP 0                               // vp: 128 x 72          = 9216
#define SLH (SVP + (KK / 2) * VP_STR)       // l:  16 x 132          = 2112
#define SRH (SLH + TI * HSTR)               // r:  16 x 132          = 2112
#define SM_WORDS (SRH + TJ * HSTR)
#define SM_BYTES (SM_WORDS * 4)             // 53760 B

__global__ __launch_bounds__(THR, 2) void mhs_mma_kernel(
    const float* __restrict__ v, float* __restrict__ out)
{
    extern __shared__ float sm[];
    uint32_t* smw = (uint32_t*)sm;
    uint32_t* vp = smw + SVP;

    const int tid = threadIdx.x;
    const int w = tid >> 5;          // 0..7 ; owns i rows 2w, 2w+1
    const int lane = tid & 31;
    const int kq = lane & 3;
    const int gp = lane >> 2;

    // Stage v as packed fp16x2 {lo=v[2kp][c], hi=v[2kp+1][c]}, cols padded to 56.
    for (int idx = tid; idx < (KK / 2) * 56; idx += THR) {
        int kp = idx / 56, c = idx - kp * 56;
        float v0 = (c < PP) ? v[(2 * kp) * PP + c] : 0.0f;
        float v1 = (c < PP) ? v[(2 * kp + 1) * PP + c] : 0.0f;
        vp[kp * VP_STR + c] = pack_f16x2(v1, v0);
    }

    for (int t = blockIdx.x; t < NTILES; t += gridDim.x) {
        const int b = t >> 8;
        const int rem = t & 255;
        const int i0 = (rem >> 4) * TI;
        const int j0 = (rem & 15) * TJ;

        __syncthreads();   // all warps done reading previous tile's l/r

        // Stage l/r tiles: 16 rows x 32 uint4 chunks each; 256 thr -> 2 iters.
        {
            const uint4* lg = (const uint4*)(g_left_h + (b * SS + i0) * KK);
            const uint4* rg = (const uint4*)(g_right_h + (b * SS + j0) * KK);
#pragma unroll
            for (int q = 0; q < 2; q++) {
                int idx = tid + q * THR;           // 0..511
                int row = idx >> 5, ch = idx & 31;
                *(uint4*)(smw + SLH + row * HSTR + ch * 4) = lg[row * 32 + ch];
                *(uint4*)(smw + SRH + row * HSTR + ch * 4) = rg[row * 32 + ch];
            }
        }
        __syncthreads();

        const uint32_t* lw0 = smw + SLH + (2 * w) * HSTR;
        const uint32_t* lw1 = lw0 + HSTR;
        const uint32_t* r0w = smw + SRH + gp * HSTR;
        const uint32_t* r1w = r0w + 8 * HSTR;

        float acc[2][NT][4];
#pragma unroll
        for (int ii = 0; ii < 2; ii++)
#pragma unroll
            for (int n = 0; n < NT; n++) {
                acc[ii][n][0] = 0.f; acc[ii][n][1] = 0.f;
                acc[ii][n][2] = 0.f; acc[ii][n][3] = 0.f;
            }

#pragma unroll 2
        for (int ks = 0; ks < KK / 16; ks++) {
            const int wA = 8 * ks + kq;
            const int wB = wA + 4;
            // shared r loads (4) + per-i l loads (2 each)
            const uint32_t r0A = r0w[wA], r0B = r0w[wB];
            const uint32_t r1A = r1w[wA], r1B = r1w[wB];
            const uint32_t lA0 = lw0[wA], lB0 = lw0[wB];
            const uint32_t lA1 = lw1[wA], lB1 = lw1[wB];

            const uint32_t a00 = tanh2h(hadd2(lA0, r0A));
            const uint32_t a01 = tanh2h(hadd2(lA0, r1A));
            const uint32_t a02 = tanh2h(hadd2(lB0, r0B));
            const uint32_t a03 = tanh2h(hadd2(lB0, r1B));
            const uint32_t a10 = tanh2h(hadd2(lA1, r0A));
            const uint32_t a11 = tanh2h(hadd2(lA1, r1A));
            const uint32_t a12 = tanh2h(hadd2(lB1, r0B));
            const uint32_t a13 = tanh2h(hadd2(lB1, r1B));

            const uint32_t* v0 = vp + wA * VP_STR + gp;
            const uint32_t* v1 = v0 + 4 * VP_STR;
#pragma unroll
            for (int n = 0; n < NT; n++) {
                const uint32_t b0 = v0[8 * n];
                const uint32_t b1 = v1[8 * n];
                mma_f16(acc[0][n], a00, a01, a02, a03, b0, b1);
                mma_f16(acc[1][n], a10, a11, a12, a13, b0, b1);
            }
        }

        // Epilogue: per i-row, c0,c1 at (j=gp, p=8n+2kq), c2,c3 at j=gp+8.
#pragma unroll
        for (int ii = 0; ii < 2; ii++) {
            const int i = i0 + 2 * w + ii;
            float* o0 = out + (size_t)((b * SS + i) * SS + j0 + gp) * PP;
            float* o1 = o0 + 8 * PP;
#pragma unroll
            for (int n = 0; n < NT; n++) {
                int p = 8 * n + 2 * kq;
                if (p < PP) {
                    *(float2*)(o0 + p) = make_float2(acc[ii][n][0], acc[ii][n][1]);
                    *(float2*)(o1 + p) = make_float2(acc[ii][n][2], acc[ii][n][3]);
                }
            }
        }
    }
}

// ---------------------------------------------------------------------------
// Launch. Inputs (metadata order): x, u_a, w_a, b_s, v. Output: float32.
// ---------------------------------------------------------------------------
extern "C" void kernel_launch(void* const* d_in, const int* in_sizes, int n_in,
                              void* d_out, int out_size)
{
    const float* x   = (const float*)d_in[0];
    const float* u_a = (const float*)d_in[1];
    const float* w_a = (const float*)d_in[2];
    const float* b_s = (const float*)d_in[3];
    const float* v   = (const float*)d_in[4];
    float* out = (float*)d_out;

    cudaFuncSetAttribute(proj_mma_kernel, cudaFuncAttributeMaxDynamicSharedMemorySize, PSM_BYTES);
    cudaFuncSetAttribute(mhs_mma_kernel, cudaFuncAttributeMaxDynamicSharedMemorySize, SM_BYTES);

    dim3 g1(KK / 64, (BS * SS) / 64, 2);
    proj_mma_kernel<<<g1, 128, PSM_BYTES>>>(x, u_a, w_a, b_s);

    mhs_mma_kernel<<<296, THR, SM_BYTES>>>(v, out);
}